// round 8
// baseline (speedup 1.0000x reference)
#include <cuda_runtime.h>
#include <cuda_fp16.h>
#include <mma.h>
#include <math.h>
#include <stdint.h>

using namespace nvcuda;

#define B_WIN  4096
#define NT     49
#define CDIM   256
#define HEADS  8
#define HDIM   32
#define KQKV   768
#define MROWS  (B_WIN * NT)          /* 200704 = 128*1568 */
#define SCALE_F 0.17677669529663687f /* 32^-0.5 */

/* -------- scratch (allocation-free: __device__ globals) -------- */
__device__ __half g_xh[(size_t)MROWS * CDIM];    /* x in fp16            */
__device__ __half g_qkvh[(size_t)MROWS * KQKV];  /* qkv in fp16          */
__device__ __half g_oh[(size_t)MROWS * CDIM];    /* attn out in fp16     */
__device__ __half g_wh[(size_t)KQKV * CDIM];     /* qkv_w fp16           */
__device__ __half g_pwh[(size_t)CDIM * CDIM];    /* proj_w fp16          */

/* -------- cp.async helpers -------- */
__device__ __forceinline__ void cp_async16(void* smem_dst, const void* gmem_src) {
    unsigned sa = (unsigned)__cvta_generic_to_shared(smem_dst);
    asm volatile("cp.async.cg.shared.global [%0], [%1], 16;\n" :: "r"(sa), "l"(gmem_src));
}
__device__ __forceinline__ void cp_commit() {
    asm volatile("cp.async.commit_group;\n" ::: "memory");
}
template <int N>
__device__ __forceinline__ void cp_wait() {
    asm volatile("cp.async.wait_group %0;\n" :: "n"(N) : "memory");
}

/* =====================================================================
 * fp32 -> fp16 convert (vectorized, n % 4 == 0)
 * ===================================================================*/
__global__ __launch_bounds__(256) void f2h_kernel(
    const float* __restrict__ in, __half* __restrict__ out, int n)
{
    int i = (blockIdx.x * 256 + threadIdx.x) * 4;
    if (i < n) {
        float4 v = *(const float4*)&in[i];
        *(half2*)&out[i]     = __floats2half2_rn(v.x, v.y);
        *(half2*)&out[i + 2] = __floats2half2_rn(v.z, v.w);
    }
}

/* =====================================================================
 * GEMM (fp16 HMMA, round-4 pipeline): C[m,n] = sum_k A[m,k]*W[n,k] + bias[n]
 * Block 128x128, BK=64, cp.async double buffer, 256 thr = 8 warps
 * (4M x 2N), warp tile 32x64 via m16n16k16 fp16->fp32.
 * __launch_bounds__(256,3): cap regs at 85 -> 3 CTAs/SM.
 * OUT_HALF=1: stage + convert to fp16.  OUT_HALF=0: direct fp32 store.
 * ===================================================================*/
#define HS_TILE  (128 * 72)               /* halves per operand tile   */
#define HS_STAGE (2 * HS_TILE)            /* halves per (A+B) stage    */
#define GEMMH_SMEM (2 * HS_STAGE * 2 + 16 * 132 * 4 + 256)

template <int OUT_HALF>
__global__ __launch_bounds__(256, 3) void gemm_h_kernel(
    const __half* __restrict__ A, const __half* __restrict__ W,
    const float* __restrict__ bias, void* __restrict__ Cv,
    int Nld, int K)
{
    extern __shared__ char smem_raw[];
    __half* Ah = (__half*)smem_raw;                 /* stage s: Ah + s*HS_STAGE */
    float*  btile = (float*)(smem_raw + 2 * HS_STAGE * 2); /* 16 x 132 */

    const int tid  = threadIdx.x;
    const int warp = tid >> 5;
    const int wm   = warp >> 1;  /* 0..3 along M */
    const int wn   = warp & 1;   /* 0..1 along N */
    const int m0   = blockIdx.y * 128;
    const int n0   = blockIdx.x * 128;
    const int nk   = K >> 6;

    const int cr = tid >> 3;       /* base row 0..31       */
    const int cc = tid & 7;        /* 16B chunk (8 halves) */

    /* issue stage 0 and 1 */
#pragma unroll
    for (int st = 0; st < 2; st++) {
        if (st < nk) {
            int kc = st * 64;
#pragma unroll
            for (int i = 0; i < 4; i++) {
                int r = cr + i * 32;
                cp_async16(&Ah[st * HS_STAGE + r * 72 + cc * 8],
                           &A[(size_t)(m0 + r) * K + kc + cc * 8]);
                cp_async16(&Ah[st * HS_STAGE + HS_TILE + r * 72 + cc * 8],
                           &W[(size_t)(n0 + r) * K + kc + cc * 8]);
            }
        }
        cp_commit();
    }

    /* bias tile: 16 identical rows */
    for (int idx = tid; idx < 16 * 128; idx += 256) {
        int row = idx >> 7, col = idx & 127;
        btile[row * 132 + col] = bias[n0 + col];
    }
    __syncthreads();

    wmma::fragment<wmma::accumulator, 16, 16, 16, float> c[2][4];
#pragma unroll
    for (int j = 0; j < 4; j++) {
        wmma::load_matrix_sync(c[0][j], &btile[wn * 64 + j * 16], 132,
                               wmma::mem_row_major);
        c[1][j] = c[0][j];
    }

    for (int kt = 0; kt < nk; kt++) {
        cp_wait<1>();
        __syncthreads();
        const __half* Ab = Ah + (kt & 1) * HS_STAGE;
        const __half* Bb = Ab + HS_TILE;

#pragma unroll
        for (int ks = 0; ks < 4; ks++) {
            wmma::fragment<wmma::matrix_a, 16, 16, 16, __half, wmma::row_major> a[2];
#pragma unroll
            for (int i = 0; i < 2; i++)
                wmma::load_matrix_sync(a[i], &Ab[(wm * 32 + i * 16) * 72 + ks * 16], 72);
#pragma unroll
            for (int j = 0; j < 4; j++) {
                wmma::fragment<wmma::matrix_b, 16, 16, 16, __half, wmma::col_major> b;
                wmma::load_matrix_sync(b, &Bb[(wn * 64 + j * 16) * 72 + ks * 16], 72);
                wmma::mma_sync(c[0][j], a[0], b, c[0][j]);
                wmma::mma_sync(c[1][j], a[1], b, c[1][j]);
            }
        }
        __syncthreads();

        int kn = kt + 2;
        if (kn < nk) {
            int kc = kn * 64, st = kt & 1;
#pragma unroll
            for (int i = 0; i < 4; i++) {
                int r = cr + i * 32;
                cp_async16(&Ah[st * HS_STAGE + r * 72 + cc * 8],
                           &A[(size_t)(m0 + r) * K + kc + cc * 8]);
                cp_async16(&Ah[st * HS_STAGE + HS_TILE + r * 72 + cc * 8],
                           &W[(size_t)(n0 + r) * K + kc + cc * 8]);
            }
        }
        cp_commit();
    }

    if (OUT_HALF) {
        float* stg = (float*)smem_raw;   /* 128 x 132 floats, fits in stages */
        __syncthreads();
#pragma unroll
        for (int i = 0; i < 2; i++)
#pragma unroll
            for (int j = 0; j < 4; j++)
                wmma::store_matrix_sync(
                    &stg[(wm * 32 + i * 16) * 132 + wn * 64 + j * 16],
                    c[i][j], 132, wmma::mem_row_major);
        __syncthreads();
        __half* Ch = (__half*)Cv;
        for (int idx = tid; idx < 128 * 64; idx += 256) {
            int row = idx >> 6, cp2 = (idx & 63) << 1;
            half2 h = __floats2half2_rn(stg[row * 132 + cp2],
                                        stg[row * 132 + cp2 + 1]);
            *(half2*)&Ch[(size_t)(m0 + row) * Nld + n0 + cp2] = h;
        }
    } else {
        float* Cf = (float*)Cv;
#pragma unroll
        for (int i = 0; i < 2; i++)
#pragma unroll
            for (int j = 0; j < 4; j++)
                wmma::store_matrix_sync(
                    &Cf[(size_t)(m0 + wm * 32 + i * 16) * Nld + n0 + wn * 64 + j * 16],
                    c[i][j], Nld, wmma::mem_row_major);
    }
}

/* =====================================================================
 * Attention v6 = round-4 v3 structure (block-wide coalesced passes,
 * block syncs) + smem savings: q/k merged, fp16 P overlays dead q/k,
 * only V pad rows zeroed. smem 42.7 KB -> 33.4 KB (6 CTAs/SM).
 * Pad-garbage safety: q/k pad rows/cols only produce S entries that are
 * never read (bias pass touches m<49 only; P cols>=49 explicitly zeroed;
 * O rows>=49 discarded at store). V pads ARE zeroed since P*V sums them.
 * ===================================================================*/
__global__ __launch_bounds__(128) void attn_kernel(
    const __half* __restrict__ qkv, const float* __restrict__ mask,
    const float* __restrict__ bias_table, float* __restrict__ attn_out,
    __half* __restrict__ o_out)
{
    __shared__ __half qk[2 * 64 * 40];   /* q: [0,2560), k: [2560,5120) */
    __shared__ __half vs[64 * 40];
    __shared__ float  ss[64 * 68];
    __shared__ float  biasS[176];
    __half* ps = qk;                     /* P overlay, stride 72: 4600 <= 5120 */

    const int tid  = threadIdx.x;
    const int warp = tid >> 5;
    const int h    = blockIdx.x;
    const int b    = blockIdx.y;

    /* zero V pad rows 49..63; gather this head's bias column */
    {
        half2 z = __floats2half2_rn(0.f, 0.f);
        half2* v2 = (half2*)vs;
        for (int i = tid; i < 15 * 20; i += 128) v2[49 * 20 + i] = z;
    }
    for (int r = tid; r < 169; r += 128) biasS[r] = __ldg(&bias_table[r * HEADS + h]);

    /* load q/k/v (half2): 49 rows x 16 half2 */
    {
        const __half* base = qkv + (size_t)b * NT * KQKV + h * HDIM;
        half2* q2 = (half2*)qk;
        half2* k2 = (half2*)(qk + 2560);
        half2* v2 = (half2*)vs;
        for (int idx = tid; idx < NT * 16; idx += 128) {
            int n = idx >> 4, d2 = idx & 15;
            const half2* src = (const half2*)(base + (size_t)n * KQKV) + d2;
            q2[n * 20 + d2] = src[0];
            k2[n * 20 + d2] = src[128];   /* +256 halves */
            v2[n * 20 + d2] = src[256];   /* +512 halves */
        }
    }
    __syncthreads();

    /* S = Q K^T (64x64, K=32 -> 2 k-steps); warp -> 16-row slab */
    {
        wmma::fragment<wmma::accumulator, 16, 16, 16, float> sc[4];
#pragma unroll
        for (int j = 0; j < 4; j++) wmma::fill_fragment(sc[j], 0.0f);
#pragma unroll
        for (int ks = 0; ks < 2; ks++) {
            wmma::fragment<wmma::matrix_a, 16, 16, 16, __half, wmma::row_major> a;
            wmma::load_matrix_sync(a, &qk[(warp * 16) * 40 + ks * 16], 40);
#pragma unroll
            for (int j = 0; j < 4; j++) {
                wmma::fragment<wmma::matrix_b, 16, 16, 16, __half, wmma::col_major> bfr;
                wmma::load_matrix_sync(bfr, &qk[2560 + (j * 16) * 40 + ks * 16], 40);
                wmma::mma_sync(sc[j], a, bfr, sc[j]);
            }
        }
#pragma unroll
        for (int j = 0; j < 4; j++)
            wmma::store_matrix_sync(&ss[(warp * 16) * 68 + j * 16], sc[j], 68,
                                    wmma::mem_row_major);
    }
    __syncthreads();   /* S staged; q/k dead -> ps overlay is now legal */

    /* attn = S*scale + bias + mask over 49x49 valid region (coalesced) */
    {
        const float* mwin = mask + (size_t)(b & 63) * NT * NT;
        for (int idx = tid; idx < NT * NT; idx += 128) {
            int n = idx / NT, m = idx - n * NT;
            int nh = n / 7, nw = n - nh * 7;
            int mh = m / 7, mw = m - mh * 7;
            int rel = (nh - mh + 6) * 13 + (nw - mw + 6);
            ss[n * 68 + m] = ss[n * 68 + m] * SCALE_F + biasS[rel] + mwin[idx];
        }
    }
    __syncthreads();

    /* softmax: 2 threads per row (garbage pad rows do harmless work) */
    {
        int n = tid >> 1, hf = tid & 1;
        float* row = &ss[n * 68];
        float mx = -1e30f;
        for (int m = hf; m < NT; m += 2) mx = fmaxf(mx, row[m]);
        mx = fmaxf(mx, __shfl_xor_sync(0xffffffffu, mx, 1));
        float sum = 0.f;
        for (int m = hf; m < NT; m += 2) {
            float e = __expf(row[m] - mx);
            row[m] = e;
            sum += e;
        }
        sum += __shfl_xor_sync(0xffffffffu, sum, 1);
        float inv = 1.0f / sum;
        for (int m = hf; m < NT; m += 2) row[m] *= inv;
    }
    __syncthreads();

    /* write attn probs (fp32) + build fp16 P tile (cols >= 49 zeroed) */
    {
        float* aout = attn_out + (size_t)(b * HEADS + h) * NT * NT;
        for (int idx = tid; idx < NT * NT; idx += 128) {
            int n = idx / NT, m = idx - n * NT;
            aout[idx] = ss[n * 68 + m];
        }
        for (int idx = tid; idx < 64 * 32; idx += 128) {
            int n = idx >> 5, m2 = (idx & 31) << 1;
            float v0 = (m2     < NT) ? ss[n * 68 + m2]     : 0.f;
            float v1 = (m2 + 1 < NT) ? ss[n * 68 + m2 + 1] : 0.f;
            *(half2*)&ps[n * 72 + m2] = __floats2half2_rn(v0, v1);
        }
    }
    __syncthreads();

    /* O = P(64x64) @ V(64x32): 4 k-steps of 16; stage into own ss rows */
    {
        wmma::fragment<wmma::accumulator, 16, 16, 16, float> oc[2];
#pragma unroll
        for (int j = 0; j < 2; j++) wmma::fill_fragment(oc[j], 0.0f);
#pragma unroll
        for (int ks = 0; ks < 4; ks++) {
            wmma::fragment<wmma::matrix_a, 16, 16, 16, __half, wmma::row_major> a;
            wmma::load_matrix_sync(a, &ps[(warp * 16) * 72 + ks * 16], 72);
#pragma unroll
            for (int j = 0; j < 2; j++) {
                wmma::fragment<wmma::matrix_b, 16, 16, 16, __half, wmma::row_major> bfr;
                wmma::load_matrix_sync(bfr, &vs[(ks * 16) * 40 + j * 16], 40);
                wmma::mma_sync(oc[j], a, bfr, oc[j]);
            }
        }
#pragma unroll
        for (int j = 0; j < 2; j++)
            wmma::store_matrix_sync(&ss[(warp * 16) * 68 + j * 16], oc[j], 68,
                                    wmma::mem_row_major);
    }
    __syncthreads();

    {
        __half* obase = o_out + (size_t)b * NT * CDIM + h * HDIM;
        for (int idx = tid; idx < NT * 16; idx += 128) {
            int n = idx >> 4, d2 = (idx & 15) << 1;
            *(half2*)&obase[(size_t)n * CDIM + d2] =
                __floats2half2_rn(ss[n * 68 + d2], ss[n * 68 + d2 + 1]);
        }
    }
}

/* ===================================================================*/
extern "C" void kernel_launch(void* const* d_in, const int* in_sizes, int n_in,
                              void* d_out, int out_size)
{
    const float* x          = (const float*)d_in[0];
    const float* mask       = (const float*)d_in[1];
    const float* qkv_w      = (const float*)d_in[2];
    const float* qkv_b      = (const float*)d_in[3];
    const float* proj_w     = (const float*)d_in[4];
    const float* proj_b     = (const float*)d_in[5];
    const float* bias_table = (const float*)d_in[6];

    float* out_part  = (float*)d_out;                       /* [200704][256] */
    float* attn_part = out_part + (size_t)MROWS * CDIM;     /* [32768][49][49] */

    __half *xh = nullptr, *qkvh = nullptr, *oh = nullptr, *wh = nullptr, *pwh = nullptr;
    cudaGetSymbolAddress((void**)&xh,   g_xh);
    cudaGetSymbolAddress((void**)&qkvh, g_qkvh);
    cudaGetSymbolAddress((void**)&oh,   g_oh);
    cudaGetSymbolAddress((void**)&wh,   g_wh);
    cudaGetSymbolAddress((void**)&pwh,  g_pwh);

    static int smem_set = 0;
    if (!smem_set) {
        cudaFuncSetAttribute(gemm_h_kernel<1>,
                             cudaFuncAttributeMaxDynamicSharedMemorySize, GEMMH_SMEM);
        cudaFuncSetAttribute(gemm_h_kernel<0>,
                             cudaFuncAttributeMaxDynamicSharedMemorySize, GEMMH_SMEM);
        smem_set = 1;
    }

    /* 0) fp16 conversions */
    f2h_kernel<<<(MROWS * CDIM / 4 + 255) / 256, 256>>>(x, xh, MROWS * CDIM);
    f2h_kernel<<<(KQKV * CDIM / 4 + 255) / 256, 256>>>(qkv_w, wh, KQKV * CDIM);
    f2h_kernel<<<(CDIM * CDIM / 4 + 255) / 256, 256>>>(proj_w, pwh, CDIM * CDIM);

    /* 1) QKV GEMM: [200704,256] @ [768,256]^T + b -> g_qkvh (fp16) */
    gemm_h_kernel<1><<<dim3(KQKV / 128, MROWS / 128), 256, GEMMH_SMEM>>>(
        xh, wh, qkv_b, qkvh, KQKV, CDIM);

    /* 2) per-(window,head) attention */
    attn_kernel<<<dim3(HEADS, B_WIN), 128>>>(
        qkvh, mask, bias_table, attn_part, oh);

    /* 3) proj GEMM: [200704,256] @ [256,256]^T + b -> out (fp32) */
    gemm_h_kernel<0><<<dim3(CDIM / 128, MROWS / 128), 256, GEMMH_SMEM>>>(
        oh, pwh, proj_b, out_part, CDIM, CDIM);
}

// round 9
// speedup vs baseline: 1.1697x; 1.1697x over previous
#include <cuda_runtime.h>
#include <cuda_fp16.h>
#include <mma.h>
#include <math.h>
#include <stdint.h>

using namespace nvcuda;

#define B_WIN  4096
#define NT     49
#define CDIM   256
#define HEADS  8
#define HDIM   32
#define KQKV   768
#define MROWS  (B_WIN * NT)          /* 200704 = 128*1568 */
#define SCALE_F 0.17677669529663687f /* 32^-0.5 */

/* -------- scratch (allocation-free: __device__ globals) -------- */
__device__ __half g_xh[(size_t)MROWS * CDIM];    /* x in fp16            */
__device__ __half g_qkvh[(size_t)MROWS * KQKV];  /* qkv in fp16          */
__device__ __half g_oh[(size_t)MROWS * CDIM];    /* attn out in fp16     */
__device__ __half g_wh[(size_t)KQKV * CDIM];     /* qkv_w fp16           */
__device__ __half g_pwh[(size_t)CDIM * CDIM];    /* proj_w fp16          */

/* -------- cp.async helpers -------- */
__device__ __forceinline__ void cp_async16(void* smem_dst, const void* gmem_src) {
    unsigned sa = (unsigned)__cvta_generic_to_shared(smem_dst);
    asm volatile("cp.async.cg.shared.global [%0], [%1], 16;\n" :: "r"(sa), "l"(gmem_src));
}
__device__ __forceinline__ void cp_commit() {
    asm volatile("cp.async.commit_group;\n" ::: "memory");
}
template <int N>
__device__ __forceinline__ void cp_wait() {
    asm volatile("cp.async.wait_group %0;\n" :: "n"(N) : "memory");
}

/* -------- FMA-pipe exp (avoids MUFU bottleneck) --------
 * e^x = 2^(x*log2e); rint via magic-number add, 2^f degree-5 poly,
 * 2^n via exponent-bit add. Valid for x in [-87, ~80]; here x <= 0.
 * Max rel err ~2.4e-6.                                            */
__device__ __forceinline__ float exp_fast(float x) {
    float y = fmaxf(x, -87.0f) * 1.44269504f;
    float t = y + 12582912.0f;                    /* 1.5*2^23 RN magic */
    int   e = __float_as_int(t) - 0x4B400000;     /* integer part      */
    float f = y - (t - 12582912.0f);              /* frac in [-.5,.5]  */
    float p =              1.33336e-3f;
    p = fmaf(p, f, 9.61813e-3f);
    p = fmaf(p, f, 5.55041e-2f);
    p = fmaf(p, f, 2.40227e-1f);
    p = fmaf(p, f, 6.93147e-1f);
    p = fmaf(p, f, 1.0f);
    return p * __int_as_float(0x3F800000 + (e << 23));
}

/* =====================================================================
 * fp32 -> fp16 convert (vectorized, n % 4 == 0)
 * ===================================================================*/
__global__ __launch_bounds__(256) void f2h_kernel(
    const float* __restrict__ in, __half* __restrict__ out, int n)
{
    int i = (blockIdx.x * 256 + threadIdx.x) * 4;
    if (i < n) {
        float4 v = *(const float4*)&in[i];
        *(half2*)&out[i]     = __floats2half2_rn(v.x, v.y);
        *(half2*)&out[i + 2] = __floats2half2_rn(v.z, v.w);
    }
}

/* =====================================================================
 * GEMM v5 (fp16 HMMA): C[m,n] = sum_k A[m,k]*W[n,k] + bias[n]
 * Block 128(M) x 64(N), BK=64, cp.async double buffer, 128 thr =
 * 4 warps (4M x 1N), warp tile 32x64 via m16n16k16 fp16->fp32.
 * smem 55.4 KB -> 4 CTAs/SM; regs unconstrained.
 * Bias added in staged epilogue (per-thread column is loop-invariant).
 * Requires M%128==0, N%64==0, K%64==0.
 * ===================================================================*/
#define G5_STRIDE 72                                /* halves per row    */
#define G5_TILEH  ((128 + 64) * G5_STRIDE)          /* halves per stage  */
#define GEMMH_SMEM (2 * G5_TILEH * 2 + 128)         /* ~55.4 KB          */

template <int OUT_HALF>
__global__ __launch_bounds__(128) void gemm_h_kernel(
    const __half* __restrict__ A, const __half* __restrict__ W,
    const float* __restrict__ bias, void* __restrict__ Cv,
    int Nld, int K)
{
    extern __shared__ char smem_raw[];
    __half* Sh = (__half*)smem_raw;   /* stage s: Sh + s*G5_TILEH; B at +128*72 */

    const int tid  = threadIdx.x;
    const int warp = tid >> 5;
    const int m0   = blockIdx.y * 128;
    const int n0   = blockIdx.x * 64;
    const int nk   = K >> 6;

    const int cr = tid >> 3;       /* base row 0..15       */
    const int cc = tid & 7;        /* 16B chunk (8 halves) */

    /* issue stage 0 and 1 */
#pragma unroll
    for (int st = 0; st < 2; st++) {
        if (st < nk) {
            int kc = st * 64;
            __half* dst = Sh + st * G5_TILEH;
#pragma unroll
            for (int i = 0; i < 8; i++) {
                int r = cr + i * 16;
                cp_async16(&dst[r * G5_STRIDE + cc * 8],
                           &A[(size_t)(m0 + r) * K + kc + cc * 8]);
            }
#pragma unroll
            for (int i = 0; i < 4; i++) {
                int r = cr + i * 16;
                cp_async16(&dst[(128 + r) * G5_STRIDE + cc * 8],
                           &W[(size_t)(n0 + r) * K + kc + cc * 8]);
            }
        }
        cp_commit();
    }

    wmma::fragment<wmma::accumulator, 16, 16, 16, float> c[2][4];
#pragma unroll
    for (int i = 0; i < 2; i++)
#pragma unroll
        for (int j = 0; j < 4; j++)
            wmma::fill_fragment(c[i][j], 0.0f);

    for (int kt = 0; kt < nk; kt++) {
        cp_wait<1>();
        __syncthreads();
        const __half* Ab = Sh + (kt & 1) * G5_TILEH;
        const __half* Bb = Ab + 128 * G5_STRIDE;

#pragma unroll
        for (int ks = 0; ks < 4; ks++) {
            wmma::fragment<wmma::matrix_a, 16, 16, 16, __half, wmma::row_major> a[2];
#pragma unroll
            for (int i = 0; i < 2; i++)
                wmma::load_matrix_sync(a[i],
                    &Ab[(warp * 32 + i * 16) * G5_STRIDE + ks * 16], G5_STRIDE);
#pragma unroll
            for (int j = 0; j < 4; j++) {
                wmma::fragment<wmma::matrix_b, 16, 16, 16, __half, wmma::col_major> b;
                wmma::load_matrix_sync(b, &Bb[(j * 16) * G5_STRIDE + ks * 16], G5_STRIDE);
                wmma::mma_sync(c[0][j], a[0], b, c[0][j]);
                wmma::mma_sync(c[1][j], a[1], b, c[1][j]);
            }
        }
        __syncthreads();

        int kn = kt + 2;
        if (kn < nk) {
            int kc = kn * 64;
            __half* dst = Sh + (kt & 1) * G5_TILEH;
#pragma unroll
            for (int i = 0; i < 8; i++) {
                int r = cr + i * 16;
                cp_async16(&dst[r * G5_STRIDE + cc * 8],
                           &A[(size_t)(m0 + r) * K + kc + cc * 8]);
            }
#pragma unroll
            for (int i = 0; i < 4; i++) {
                int r = cr + i * 16;
                cp_async16(&dst[(128 + r) * G5_STRIDE + cc * 8],
                           &W[(size_t)(n0 + r) * K + kc + cc * 8]);
            }
        }
        cp_commit();
    }

    /* staged epilogue with bias (thread's column pair is loop-invariant) */
    float* stg = (float*)smem_raw;   /* 128 x 68 floats = 34.8 KB */
    __syncthreads();
#pragma unroll
    for (int i = 0; i < 2; i++)
#pragma unroll
        for (int j = 0; j < 4; j++)
            wmma::store_matrix_sync(&stg[(warp * 32 + i * 16) * 68 + j * 16],
                                    c[i][j], 68, wmma::mem_row_major);
    __syncthreads();

    const int cp2 = (tid & 31) << 1;             /* fixed column pair */
    const float b0 = bias[n0 + cp2];
    const float b1 = bias[n0 + cp2 + 1];
    if (OUT_HALF) {
        __half* Ch = (__half*)Cv;
#pragma unroll
        for (int k = 0; k < 32; k++) {
            int row = (tid + k * 128) >> 5;
            *(half2*)&Ch[(size_t)(m0 + row) * Nld + n0 + cp2] =
                __floats2half2_rn(stg[row * 68 + cp2] + b0,
                                  stg[row * 68 + cp2 + 1] + b1);
        }
    } else {
        float* Cf = (float*)Cv;
#pragma unroll
        for (int k = 0; k < 32; k++) {
            int row = (tid + k * 128) >> 5;
            float2 o = make_float2(stg[row * 68 + cp2] + b0,
                                   stg[row * 68 + cp2 + 1] + b1);
            *(float2*)&Cf[(size_t)(m0 + row) * Nld + n0 + cp2] = o;
        }
    }
}

/* =====================================================================
 * Attention (round-4 structure + exp_fast): one block per (b, h).
 * ===================================================================*/
__global__ __launch_bounds__(128) void attn_kernel(
    const __half* __restrict__ qkv, const float* __restrict__ mask,
    const float* __restrict__ bias_table, float* __restrict__ attn_out,
    __half* __restrict__ o_out)
{
    __shared__ __half qk[2 * 64 * 40];   /* q: [0,2560), k: [2560,5120) */
    __shared__ __half vs[64 * 40];
    __shared__ float  ss[64 * 68];
    __shared__ float  biasS[176];
    __half* ps = qk;                     /* P overlay, stride 72 */

    const int tid  = threadIdx.x;
    const int warp = tid >> 5;
    const int h    = blockIdx.x;
    const int b    = blockIdx.y;

    /* zero V pad rows 49..63; gather this head's bias column */
    {
        half2 z = __floats2half2_rn(0.f, 0.f);
        half2* v2 = (half2*)vs;
        for (int i = tid; i < 15 * 20; i += 128) v2[49 * 20 + i] = z;
    }
    for (int r = tid; r < 169; r += 128) biasS[r] = __ldg(&bias_table[r * HEADS + h]);

    /* load q/k/v (half2): 49 rows x 16 half2 */
    {
        const __half* base = qkv + (size_t)b * NT * KQKV + h * HDIM;
        half2* q2 = (half2*)qk;
        half2* k2 = (half2*)(qk + 2560);
        half2* v2 = (half2*)vs;
        for (int idx = tid; idx < NT * 16; idx += 128) {
            int n = idx >> 4, d2 = idx & 15;
            const half2* src = (const half2*)(base + (size_t)n * KQKV) + d2;
            q2[n * 20 + d2] = src[0];
            k2[n * 20 + d2] = src[128];
            v2[n * 20 + d2] = src[256];
        }
    }
    __syncthreads();

    /* S = Q K^T (64x64, K=32); warp -> 16-row slab */
    {
        wmma::fragment<wmma::accumulator, 16, 16, 16, float> sc[4];
#pragma unroll
        for (int j = 0; j < 4; j++) wmma::fill_fragment(sc[j], 0.0f);
#pragma unroll
        for (int ks = 0; ks < 2; ks++) {
            wmma::fragment<wmma::matrix_a, 16, 16, 16, __half, wmma::row_major> a;
            wmma::load_matrix_sync(a, &qk[(warp * 16) * 40 + ks * 16], 40);
#pragma unroll
            for (int j = 0; j < 4; j++) {
                wmma::fragment<wmma::matrix_b, 16, 16, 16, __half, wmma::col_major> bfr;
                wmma::load_matrix_sync(bfr, &qk[2560 + (j * 16) * 40 + ks * 16], 40);
                wmma::mma_sync(sc[j], a, bfr, sc[j]);
            }
        }
#pragma unroll
        for (int j = 0; j < 4; j++)
            wmma::store_matrix_sync(&ss[(warp * 16) * 68 + j * 16], sc[j], 68,
                                    wmma::mem_row_major);
    }
    __syncthreads();   /* S staged; q/k dead -> P overlay legal */

    /* attn = S*scale + bias + mask (coalesced, valid region) */
    {
        const float* mwin = mask + (size_t)(b & 63) * NT * NT;
        for (int idx = tid; idx < NT * NT; idx += 128) {
            int n = idx / NT, m = idx - n * NT;
            int nh = n / 7, nw = n - nh * 7;
            int mh = m / 7, mw = m - mh * 7;
            int rel = (nh - mh + 6) * 13 + (nw - mw + 6);
            ss[n * 68 + m] = ss[n * 68 + m] * SCALE_F + biasS[rel] + mwin[idx];
        }
    }
    __syncthreads();

    /* softmax: 2 threads per row, exp on FMA pipe */
    {
        int n = tid >> 1, hf = tid & 1;
        float* row = &ss[n * 68];
        float mx = -1e30f;
        for (int m = hf; m < NT; m += 2) mx = fmaxf(mx, row[m]);
        mx = fmaxf(mx, __shfl_xor_sync(0xffffffffu, mx, 1));
        float sum = 0.f;
        for (int m = hf; m < NT; m += 2) {
            float e = exp_fast(row[m] - mx);
            row[m] = e;
            sum += e;
        }
        sum += __shfl_xor_sync(0xffffffffu, sum, 1);
        float inv = 1.0f / sum;
        for (int m = hf; m < NT; m += 2) row[m] *= inv;
    }
    __syncthreads();

    /* write attn probs + build fp16 P tile (cols >= 49 zeroed) */
    {
        float* aout = attn_out + (size_t)(b * HEADS + h) * NT * NT;
        for (int idx = tid; idx < NT * NT; idx += 128) {
            int n = idx / NT, m = idx - n * NT;
            aout[idx] = ss[n * 68 + m];
        }
        for (int idx = tid; idx < 64 * 32; idx += 128) {
            int n = idx >> 5, m2 = (idx & 31) << 1;
            float v0 = (m2     < NT) ? ss[n * 68 + m2]     : 0.f;
            float v1 = (m2 + 1 < NT) ? ss[n * 68 + m2 + 1] : 0.f;
            *(half2*)&ps[n * 72 + m2] = __floats2half2_rn(v0, v1);
        }
    }
    __syncthreads();

    /* O = P(64x64) @ V(64x32) */
    {
        wmma::fragment<wmma::accumulator, 16, 16, 16, float> oc[2];
#pragma unroll
        for (int j = 0; j < 2; j++) wmma::fill_fragment(oc[j], 0.0f);
#pragma unroll
        for (int ks = 0; ks < 4; ks++) {
            wmma::fragment<wmma::matrix_a, 16, 16, 16, __half, wmma::row_major> a;
            wmma::load_matrix_sync(a, &ps[(warp * 16) * 72 + ks * 16], 72);
#pragma unroll
            for (int j = 0; j < 2; j++) {
                wmma::fragment<wmma::matrix_b, 16, 16, 16, __half, wmma::row_major> bfr;
                wmma::load_matrix_sync(bfr, &vs[(ks * 16) * 40 + j * 16], 40);
                wmma::mma_sync(oc[j], a, bfr, oc[j]);
            }
        }
#pragma unroll
        for (int j = 0; j < 2; j++)
            wmma::store_matrix_sync(&ss[(warp * 16) * 68 + j * 16], oc[j], 68,
                                    wmma::mem_row_major);
    }
    __syncthreads();

    {
        __half* obase = o_out + (size_t)b * NT * CDIM + h * HDIM;
        for (int idx = tid; idx < NT * 16; idx += 128) {
            int n = idx >> 4, d2 = (idx & 15) << 1;
            *(half2*)&obase[(size_t)n * CDIM + d2] =
                __floats2half2_rn(ss[n * 68 + d2], ss[n * 68 + d2 + 1]);
        }
    }
}

/* ===================================================================*/
extern "C" void kernel_launch(void* const* d_in, const int* in_sizes, int n_in,
                              void* d_out, int out_size)
{
    const float* x          = (const float*)d_in[0];
    const float* mask       = (const float*)d_in[1];
    const float* qkv_w      = (const float*)d_in[2];
    const float* qkv_b      = (const float*)d_in[3];
    const float* proj_w     = (const float*)d_in[4];
    const float* proj_b     = (const float*)d_in[5];
    const float* bias_table = (const float*)d_in[6];

    float* out_part  = (float*)d_out;                       /* [200704][256] */
    float* attn_part = out_part + (size_t)MROWS * CDIM;     /* [32768][49][49] */

    __half *xh = nullptr, *qkvh = nullptr, *oh = nullptr, *wh = nullptr, *pwh = nullptr;
    cudaGetSymbolAddress((void**)&xh,   g_xh);
    cudaGetSymbolAddress((void**)&qkvh, g_qkvh);
    cudaGetSymbolAddress((void**)&oh,   g_oh);
    cudaGetSymbolAddress((void**)&wh,   g_wh);
    cudaGetSymbolAddress((void**)&pwh,  g_pwh);

    static int smem_set = 0;
    if (!smem_set) {
        cudaFuncSetAttribute(gemm_h_kernel<1>,
                             cudaFuncAttributeMaxDynamicSharedMemorySize, GEMMH_SMEM);
        cudaFuncSetAttribute(gemm_h_kernel<0>,
                             cudaFuncAttributeMaxDynamicSharedMemorySize, GEMMH_SMEM);
        smem_set = 1;
    }

    /* 0) fp16 conversions */
    f2h_kernel<<<(MROWS * CDIM / 4 + 255) / 256, 256>>>(x, xh, MROWS * CDIM);
    f2h_kernel<<<(KQKV * CDIM / 4 + 255) / 256, 256>>>(qkv_w, wh, KQKV * CDIM);
    f2h_kernel<<<(CDIM * CDIM / 4 + 255) / 256, 256>>>(proj_w, pwh, CDIM * CDIM);

    /* 1) QKV GEMM: [200704,256] @ [768,256]^T + b -> g_qkvh (fp16) */
    gemm_h_kernel<1><<<dim3(KQKV / 64, MROWS / 128), 128, GEMMH_SMEM>>>(
        xh, wh, qkv_b, qkvh, KQKV, CDIM);

    /* 2) per-(window,head) attention */
    attn_kernel<<<dim3(HEADS, B_WIN), 128>>>(
        qkvh, mask, bias_table, attn_part, oh);

    /* 3) proj GEMM: [200704,256] @ [256,256]^T + b -> out (fp32) */
    gemm_h_kernel<0><<<dim3(CDIM / 64, MROWS / 128), 128, GEMMH_SMEM>>>(
        oh, pwh, proj_b, out_part, CDIM, CDIM);
}

// round 10
// speedup vs baseline: 1.2654x; 1.0818x over previous
#include <cuda_runtime.h>
#include <cuda_fp16.h>
#include <mma.h>
#include <math.h>
#include <stdint.h>

using namespace nvcuda;

#define B_WIN  4096
#define NT     49
#define CDIM   256
#define HEADS  8
#define HDIM   32
#define KQKV   768
#define MROWS  (B_WIN * NT)          /* 200704 = 128*1568 */
#define SCALE_F 0.17677669529663687f /* 32^-0.5 */

/* -------- scratch (allocation-free: __device__ globals) -------- */
__device__ __half g_xh[(size_t)MROWS * CDIM];    /* x in fp16            */
__device__ __half g_qkvh[(size_t)MROWS * KQKV];  /* qkv in fp16          */
__device__ __half g_oh[(size_t)MROWS * CDIM];    /* attn out in fp16     */
__device__ __half g_wh[(size_t)KQKV * CDIM];     /* qkv_w fp16           */
__device__ __half g_pwh[(size_t)CDIM * CDIM];    /* proj_w fp16          */

/* -------- cp.async helpers -------- */
__device__ __forceinline__ void cp_async16(void* smem_dst, const void* gmem_src) {
    unsigned sa = (unsigned)__cvta_generic_to_shared(smem_dst);
    asm volatile("cp.async.cg.shared.global [%0], [%1], 16;\n" :: "r"(sa), "l"(gmem_src));
}
__device__ __forceinline__ void cp_commit() {
    asm volatile("cp.async.commit_group;\n" ::: "memory");
}
template <int N>
__device__ __forceinline__ void cp_wait() {
    asm volatile("cp.async.wait_group %0;\n" :: "n"(N) : "memory");
}

/* -------- FMA-pipe exp -------- */
__device__ __forceinline__ float exp_fast(float x) {
    float y = fmaxf(x, -87.0f) * 1.44269504f;
    float t = y + 12582912.0f;                    /* 1.5*2^23 RN magic */
    int   e = __float_as_int(t) - 0x4B400000;
    float f = y - (t - 12582912.0f);
    float p =              1.33336e-3f;
    p = fmaf(p, f, 9.61813e-3f);
    p = fmaf(p, f, 5.55041e-2f);
    p = fmaf(p, f, 2.40227e-1f);
    p = fmaf(p, f, 6.93147e-1f);
    p = fmaf(p, f, 1.0f);
    return p * __int_as_float(0x3F800000 + (e << 23));
}

/* =====================================================================
 * fp32 -> fp16 convert
 * ===================================================================*/
__global__ __launch_bounds__(256) void f2h_kernel(
    const float* __restrict__ in, __half* __restrict__ out, int n)
{
    int i = (blockIdx.x * 256 + threadIdx.x) * 4;
    if (i < n) {
        float4 v = *(const float4*)&in[i];
        *(half2*)&out[i]     = __floats2half2_rn(v.x, v.y);
        *(half2*)&out[i + 2] = __floats2half2_rn(v.z, v.w);
    }
}

/* =====================================================================
 * GEMM v5 (unchanged from round 9): 128x64 block, BK=64, double buffer.
 * ===================================================================*/
#define G5_STRIDE 72
#define G5_TILEH  ((128 + 64) * G5_STRIDE)
#define GEMMH_SMEM (2 * G5_TILEH * 2 + 128)

template <int OUT_HALF>
__global__ __launch_bounds__(128) void gemm_h_kernel(
    const __half* __restrict__ A, const __half* __restrict__ W,
    const float* __restrict__ bias, void* __restrict__ Cv,
    int Nld, int K)
{
    extern __shared__ char smem_raw[];
    __half* Sh = (__half*)smem_raw;

    const int tid  = threadIdx.x;
    const int warp = tid >> 5;
    const int m0   = blockIdx.y * 128;
    const int n0   = blockIdx.x * 64;
    const int nk   = K >> 6;

    const int cr = tid >> 3;
    const int cc = tid & 7;

#pragma unroll
    for (int st = 0; st < 2; st++) {
        if (st < nk) {
            int kc = st * 64;
            __half* dst = Sh + st * G5_TILEH;
#pragma unroll
            for (int i = 0; i < 8; i++) {
                int r = cr + i * 16;
                cp_async16(&dst[r * G5_STRIDE + cc * 8],
                           &A[(size_t)(m0 + r) * K + kc + cc * 8]);
            }
#pragma unroll
            for (int i = 0; i < 4; i++) {
                int r = cr + i * 16;
                cp_async16(&dst[(128 + r) * G5_STRIDE + cc * 8],
                           &W[(size_t)(n0 + r) * K + kc + cc * 8]);
            }
        }
        cp_commit();
    }

    wmma::fragment<wmma::accumulator, 16, 16, 16, float> c[2][4];
#pragma unroll
    for (int i = 0; i < 2; i++)
#pragma unroll
        for (int j = 0; j < 4; j++)
            wmma::fill_fragment(c[i][j], 0.0f);

    for (int kt = 0; kt < nk; kt++) {
        cp_wait<1>();
        __syncthreads();
        const __half* Ab = Sh + (kt & 1) * G5_TILEH;
        const __half* Bb = Ab + 128 * G5_STRIDE;

#pragma unroll
        for (int ks = 0; ks < 4; ks++) {
            wmma::fragment<wmma::matrix_a, 16, 16, 16, __half, wmma::row_major> a[2];
#pragma unroll
            for (int i = 0; i < 2; i++)
                wmma::load_matrix_sync(a[i],
                    &Ab[(warp * 32 + i * 16) * G5_STRIDE + ks * 16], G5_STRIDE);
#pragma unroll
            for (int j = 0; j < 4; j++) {
                wmma::fragment<wmma::matrix_b, 16, 16, 16, __half, wmma::col_major> b;
                wmma::load_matrix_sync(b, &Bb[(j * 16) * G5_STRIDE + ks * 16], G5_STRIDE);
                wmma::mma_sync(c[0][j], a[0], b, c[0][j]);
                wmma::mma_sync(c[1][j], a[1], b, c[1][j]);
            }
        }
        __syncthreads();

        int kn = kt + 2;
        if (kn < nk) {
            int kc = kn * 64;
            __half* dst = Sh + (kt & 1) * G5_TILEH;
#pragma unroll
            for (int i = 0; i < 8; i++) {
                int r = cr + i * 16;
                cp_async16(&dst[r * G5_STRIDE + cc * 8],
                           &A[(size_t)(m0 + r) * K + kc + cc * 8]);
            }
#pragma unroll
            for (int i = 0; i < 4; i++) {
                int r = cr + i * 16;
                cp_async16(&dst[(128 + r) * G5_STRIDE + cc * 8],
                           &W[(size_t)(n0 + r) * K + kc + cc * 8]);
            }
        }
        cp_commit();
    }

    float* stg = (float*)smem_raw;
    __syncthreads();
#pragma unroll
    for (int i = 0; i < 2; i++)
#pragma unroll
        for (int j = 0; j < 4; j++)
            wmma::store_matrix_sync(&stg[(warp * 32 + i * 16) * 68 + j * 16],
                                    c[i][j], 68, wmma::mem_row_major);
    __syncthreads();

    const int cp2 = (tid & 31) << 1;
    const float b0 = bias[n0 + cp2];
    const float b1 = bias[n0 + cp2 + 1];
    if (OUT_HALF) {
        __half* Ch = (__half*)Cv;
#pragma unroll
        for (int k = 0; k < 32; k++) {
            int row = (tid + k * 128) >> 5;
            *(half2*)&Ch[(size_t)(m0 + row) * Nld + n0 + cp2] =
                __floats2half2_rn(stg[row * 68 + cp2] + b0,
                                  stg[row * 68 + cp2 + 1] + b1);
        }
    } else {
        float* Cf = (float*)Cv;
#pragma unroll
        for (int k = 0; k < 32; k++) {
            int row = (tid + k * 128) >> 5;
            float2 o = make_float2(stg[row * 68 + cp2] + b0,
                                   stg[row * 68 + cp2 + 1] + b1);
            *(float2*)&Cf[(size_t)(m0 + row) * Nld + n0 + cp2] = o;
        }
    }
}

/* =====================================================================
 * Attention v7: one block = one window x TWO heads (pipelined).
 * grid (4, 4096), 128 threads. Unit u = head h0+u.
 * cp.async loads for both units issued up front; unit1's loads
 * complete under unit0's compute.
 * rel index via t[n]-t[m]+84 identity (t[i] = (i/7)*13 + i%7).
 * ===================================================================*/
#define AT_STR  40                    /* halves per tile row       */
#define AT_TILE (64 * AT_STR)         /* 2560 halves per operand   */
#define AT_UNIT (3 * AT_TILE)         /* q|k|v per unit            */

__global__ __launch_bounds__(128) void attn_kernel(
    const __half* __restrict__ qkv, const float* __restrict__ mask,
    const float* __restrict__ bias_table, float* __restrict__ attn_out,
    __half* __restrict__ o_out)
{
    __shared__ __half tiles[2 * AT_UNIT];   /* [u][q|k|v], 30720B */
    __shared__ float  ss[64 * 68];
    __shared__ float  biasS[2][176];
    __shared__ int    tS[64];

    const int tid  = threadIdx.x;
    const int warp = tid >> 5;
    const int h0   = blockIdx.x * 2;
    const int b    = blockIdx.y;

    /* ---- issue cp.async for both units first (start DRAM early) ---- */
    const __half* wbase = qkv + (size_t)b * NT * KQKV;
#pragma unroll
    for (int u = 0; u < 2; u++) {
        const __half* hbase = wbase + (h0 + u) * HDIM;
        __half* dstu = tiles + u * AT_UNIT;
        /* 49 rows x 12 chunks (4 per operand) of 16B */
        for (int idx = tid; idx < NT * 12; idx += 128) {
            int r    = idx / 12;
            int c    = idx - r * 12;
            int seg  = c >> 2;          /* 0=q 1=k 2=v */
            int off8 = (c & 3) * 8;     /* halves      */
            cp_async16(&dstu[seg * AT_TILE + r * AT_STR + off8],
                       &hbase[(size_t)r * KQKV + seg * 256 + off8]);
        }
        cp_commit();
    }

    /* ---- fills that overlap the loads ---- */
    {   /* zero V pad rows 49..63 for both units */
        half2 z = __floats2half2_rn(0.f, 0.f);
        for (int i = tid; i < 2 * 15 * (AT_STR / 2); i += 128) {
            int u = i < 15 * (AT_STR / 2) ? 0 : 1;
            int j = i - u * 15 * (AT_STR / 2);
            ((half2*)(tiles + u * AT_UNIT + 2 * AT_TILE + NT * AT_STR))[j] = z;
        }
    }
    for (int r = tid; r < 169; r += 128) {
        biasS[0][r] = __ldg(&bias_table[r * HEADS + h0]);
        biasS[1][r] = __ldg(&bias_table[r * HEADS + h0 + 1]);
    }
    if (tid < 64) {
        int q7 = tid / 7;
        tS[tid] = q7 * 13 + (tid - q7 * 7);   /* valid for tid<49, harmless after */
    }

    const float* mwin = mask + (size_t)(b & 63) * NT * NT;

#pragma unroll
    for (int u = 0; u < 2; u++) {
        if (u == 0) cp_wait<1>(); else cp_wait<0>();
        __syncthreads();

        const __half* qs_ = tiles + u * AT_UNIT;
        const __half* ks_ = qs_ + AT_TILE;
        const __half* vs_ = qs_ + 2 * AT_TILE;
        __half* ps = (__half*)(tiles + u * AT_UNIT);  /* P overlay on dead q/k:
                                                         64*72=4608 <= 5120 */

        /* S = Q K^T (64x64, K=32) */
        {
            wmma::fragment<wmma::accumulator, 16, 16, 16, float> sc[4];
#pragma unroll
            for (int j = 0; j < 4; j++) wmma::fill_fragment(sc[j], 0.0f);
#pragma unroll
            for (int ks = 0; ks < 2; ks++) {
                wmma::fragment<wmma::matrix_a, 16, 16, 16, __half, wmma::row_major> a;
                wmma::load_matrix_sync(a, &qs_[(warp * 16) * AT_STR + ks * 16], AT_STR);
#pragma unroll
                for (int j = 0; j < 4; j++) {
                    wmma::fragment<wmma::matrix_b, 16, 16, 16, __half, wmma::col_major> bf;
                    wmma::load_matrix_sync(bf, &ks_[(j * 16) * AT_STR + ks * 16], AT_STR);
                    wmma::mma_sync(sc[j], a, bf, sc[j]);
                }
            }
#pragma unroll
            for (int j = 0; j < 4; j++)
                wmma::store_matrix_sync(&ss[(warp * 16) * 68 + j * 16], sc[j], 68,
                                        wmma::mem_row_major);
        }
        __syncthreads();   /* S staged; this unit's q/k now dead */

        /* attn = S*scale + bias + mask (rel via tS identity) */
        {
            const float* bb = biasS[u];
            for (int idx = tid; idx < NT * NT; idx += 128) {
                int n = idx / NT, m = idx - n * NT;
                int rel = tS[n] - tS[m] + 84;
                ss[n * 68 + m] = ss[n * 68 + m] * SCALE_F + bb[rel] + mwin[idx];
            }
        }
        __syncthreads();

        /* softmax: 2 threads per row */
        {
            int n = tid >> 1, hf = tid & 1;
            float* row = &ss[n * 68];
            float mx = -1e30f;
            for (int m = hf; m < NT; m += 2) mx = fmaxf(mx, row[m]);
            mx = fmaxf(mx, __shfl_xor_sync(0xffffffffu, mx, 1));
            float sum = 0.f;
            for (int m = hf; m < NT; m += 2) {
                float e = exp_fast(row[m] - mx);
                row[m] = e;
                sum += e;
            }
            sum += __shfl_xor_sync(0xffffffffu, sum, 1);
            float inv = 1.0f / sum;
            for (int m = hf; m < NT; m += 2) row[m] *= inv;
        }
        __syncthreads();

        /* merged: write attn probs + build fp16 P (cols >= 49 zeroed) */
        {
            float* aout = attn_out + (size_t)(b * HEADS + h0 + u) * NT * NT;
            for (int idx = tid; idx < 64 * 32; idx += 128) {
                int n = idx >> 5, m2 = (idx & 31) << 1;
                float v0 = (m2     < NT) ? ss[n * 68 + m2]     : 0.f;
                float v1 = (m2 + 1 < NT) ? ss[n * 68 + m2 + 1] : 0.f;
                *(half2*)&ps[n * 72 + m2] = __floats2half2_rn(v0, v1);
                if (n < NT) {
                    if (m2     < NT) aout[n * NT + m2]     = v0;
                    if (m2 + 1 < NT) aout[n * NT + m2 + 1] = v1;
                }
            }
        }
        __syncthreads();

        /* O = P @ V; stage to own ss rows; store fp16 (warp-private) */
        {
            wmma::fragment<wmma::accumulator, 16, 16, 16, float> oc[2];
#pragma unroll
            for (int j = 0; j < 2; j++) wmma::fill_fragment(oc[j], 0.0f);
#pragma unroll
            for (int ks = 0; ks < 4; ks++) {
                wmma::fragment<wmma::matrix_a, 16, 16, 16, __half, wmma::row_major> a;
                wmma::load_matrix_sync(a, &ps[(warp * 16) * 72 + ks * 16], 72);
#pragma unroll
                for (int j = 0; j < 2; j++) {
                    wmma::fragment<wmma::matrix_b, 16, 16, 16, __half, wmma::row_major> bf;
                    wmma::load_matrix_sync(bf, &vs_[(ks * 16) * AT_STR + j * 16], AT_STR);
                    wmma::mma_sync(oc[j], a, bf, oc[j]);
                }
            }
#pragma unroll
            for (int j = 0; j < 2; j++)
                wmma::store_matrix_sync(&ss[(warp * 16) * 68 + j * 16], oc[j], 68,
                                        wmma::mem_row_major);
            __syncwarp();
            /* each warp stores its own 16 rows (rows < 49) */
            __half* obase = o_out + (size_t)b * NT * CDIM + (h0 + u) * HDIM;
            int lane = tid & 31;
            for (int idx = lane; idx < 16 * 16; idx += 32) {
                int r = idx >> 4, d2 = (idx & 15) << 1, n = warp * 16 + r;
                if (n < NT)
                    *(half2*)&obase[(size_t)n * CDIM + d2] =
                        __floats2half2_rn(ss[n * 68 + d2], ss[n * 68 + d2 + 1]);
            }
        }
        /* next unit's top __syncthreads covers ss reuse */
    }
}

/* ===================================================================*/
extern "C" void kernel_launch(void* const* d_in, const int* in_sizes, int n_in,
                              void* d_out, int out_size)
{
    const float* x          = (const float*)d_in[0];
    const float* mask       = (const float*)d_in[1];
    const float* qkv_w      = (const float*)d_in[2];
    const float* qkv_b      = (const float*)d_in[3];
    const float* proj_w     = (const float*)d_in[4];
    const float* proj_b     = (const float*)d_in[5];
    const float* bias_table = (const float*)d_in[6];

    float* out_part  = (float*)d_out;                       /* [200704][256] */
    float* attn_part = out_part + (size_t)MROWS * CDIM;     /* [32768][49][49] */

    __half *xh = nullptr, *qkvh = nullptr, *oh = nullptr, *wh = nullptr, *pwh = nullptr;
    cudaGetSymbolAddress((void**)&xh,   g_xh);
    cudaGetSymbolAddress((void**)&qkvh, g_qkvh);
    cudaGetSymbolAddress((void**)&oh,   g_oh);
    cudaGetSymbolAddress((void**)&wh,   g_wh);
    cudaGetSymbolAddress((void**)&pwh,  g_pwh);

    static int smem_set = 0;
    if (!smem_set) {
        cudaFuncSetAttribute(gemm_h_kernel<1>,
                             cudaFuncAttributeMaxDynamicSharedMemorySize, GEMMH_SMEM);
        cudaFuncSetAttribute(gemm_h_kernel<0>,
                             cudaFuncAttributeMaxDynamicSharedMemorySize, GEMMH_SMEM);
        smem_set = 1;
    }

    /* 0) fp16 conversions */
    f2h_kernel<<<(MROWS * CDIM / 4 + 255) / 256, 256>>>(x, xh, MROWS * CDIM);
    f2h_kernel<<<(KQKV * CDIM / 4 + 255) / 256, 256>>>(qkv_w, wh, KQKV * CDIM);
    f2h_kernel<<<(CDIM * CDIM / 4 + 255) / 256, 256>>>(proj_w, pwh, CDIM * CDIM);

    /* 1) QKV GEMM */
    gemm_h_kernel<1><<<dim3(KQKV / 64, MROWS / 128), 128, GEMMH_SMEM>>>(
        xh, wh, qkv_b, qkvh, KQKV, CDIM);

    /* 2) attention: one block per (window, head-pair) */
    attn_kernel<<<dim3(HEADS / 2, B_WIN), 128>>>(
        qkvh, mask, bias_table, attn_part, oh);

    /* 3) proj GEMM */
    gemm_h_kernel<0><<<dim3(CDIM / 64, MROWS / 128), 128, GEMMH_SMEM>>>(
        oh, pwh, proj_b, out_part, CDIM, CDIM);
}